// round 7
// baseline (speedup 1.0000x reference)
#include <cuda_runtime.h>
#include <math.h>

#define Nn   1048576
#define Dd   128
#define Gg   4096
#define HID  50
#define GDIM 201
#define TAILC 33
#define OUTC 234   // 201 + 33

// ---------------- device scratch (no runtime allocation allowed) ----------------
__device__ int   d_start[Gg + 1];       // segment row boundaries
__device__ float d_aggr [Gg * 512];     // [g][mean(128) | std(128) | max(128) | min(128)]
__device__ float d_W1t  [HID * 512];    // W1 transposed: [j][k]

// ---------------- kernel 0: segment boundaries via linear boundary scan ----------------
__global__ __launch_bounds__(256) void bounds_kernel(const int* __restrict__ batch) {
    int i = blockIdx.x * 256 + threadIdx.x;          // 0 .. Nn/4-1
    const int4* b4 = reinterpret_cast<const int4*>(batch);
    int4 b = __ldg(&b4[i]);
    int prev = (i == 0) ? -1 : __ldg(&batch[i * 4 - 1]);

    int pos = i * 4;
    for (int g = prev + 1; g <= b.x; g++) d_start[g] = pos;
    for (int g = b.x  + 1; g <= b.y; g++) d_start[g] = pos + 1;
    for (int g = b.y  + 1; g <= b.z; g++) d_start[g] = pos + 2;
    for (int g = b.z  + 1; g <= b.w; g++) d_start[g] = pos + 3;

    if (i == Nn / 4 - 1) {
        for (int g = b.w + 1; g <= Gg; g++) d_start[g] = Nn;
    }
}

// ---------------- kernel 0b: transpose W1 [512][50] -> [50][512] ----------------
__global__ __launch_bounds__(512) void w1t_kernel(const float* __restrict__ W1) {
    int j = blockIdx.x;            // 0..49
    int k = threadIdx.x;           // 0..511
    d_W1t[j * 512 + k] = __ldg(&W1[k * HID + j]);
}

// ---------------- kernel A: one block per segment, software-pipelined loads ----------------
__global__ __launch_bounds__(128) void seg_kernel(const float4* __restrict__ x4) {
    __shared__ __align__(16) float sm_s[512];
    __shared__ __align__(16) float sm_q[512];
    __shared__ __align__(16) float sm_x[512];
    __shared__ __align__(16) float sm_n[512];

    int g    = blockIdx.x;
    int lane = threadIdx.x & 31;
    int w    = threadIdx.x >> 5;

    int lo  = d_start[g];
    int hi  = d_start[g + 1];
    int len = hi - lo;
    int chunk = (len + 3) >> 2;
    int rb = lo + w * chunk;
    int re = min(rb + chunk, hi);
    int nrows = max(re - rb, 0);
    int nit   = nrows >> 2;          // groups of 4 rows

    float4 s  = make_float4(0.f, 0.f, 0.f, 0.f);
    float4 q  = make_float4(0.f, 0.f, 0.f, 0.f);
    float4 mx = make_float4(-INFINITY, -INFINITY, -INFINITY, -INFINITY);
    float4 mn = make_float4( INFINITY,  INFINITY,  INFINITY,  INFINITY);

#define ACC(V)                                                                  \
        s.x += (V).x; s.y += (V).y; s.z += (V).z; s.w += (V).w;                 \
        q.x = fmaf((V).x,(V).x,q.x); q.y = fmaf((V).y,(V).y,q.y);               \
        q.z = fmaf((V).z,(V).z,q.z); q.w = fmaf((V).w,(V).w,q.w);               \
        mx.x = fmaxf(mx.x,(V).x); mx.y = fmaxf(mx.y,(V).y);                     \
        mx.z = fmaxf(mx.z,(V).z); mx.w = fmaxf(mx.w,(V).w);                     \
        mn.x = fminf(mn.x,(V).x); mn.y = fminf(mn.y,(V).y);                     \
        mn.z = fminf(mn.z,(V).z); mn.w = fminf(mn.w,(V).w);

    const float4* p = x4 + (size_t)rb * 32 + lane;

    if (nit > 0) {
        float4 a0 = __ldg(p);
        float4 a1 = __ldg(p + 32);
        float4 a2 = __ldg(p + 64);
        float4 a3 = __ldg(p + 96);
        p += 128;
#pragma unroll 1
        for (int t = 1; t < nit; t++) {
            float4 n0 = __ldg(p);
            float4 n1 = __ldg(p + 32);
            float4 n2 = __ldg(p + 64);
            float4 n3 = __ldg(p + 96);
            p += 128;
            ACC(a0) ACC(a1) ACC(a2) ACC(a3)
            a0 = n0; a1 = n1; a2 = n2; a3 = n3;
        }
        ACC(a0) ACC(a1) ACC(a2) ACC(a3)
    }
    for (int r = rb + nit * 4; r < re; r++) {
        float4 v = __ldg(p);
        p += 32;
        ACC(v)
    }
#undef ACC

    reinterpret_cast<float4*>(sm_s)[w * 32 + lane] = s;
    reinterpret_cast<float4*>(sm_q)[w * 32 + lane] = q;
    reinterpret_cast<float4*>(sm_x)[w * 32 + lane] = mx;
    reinterpret_cast<float4*>(sm_n)[w * 32 + lane] = mn;
    __syncthreads();

    int col = threadIdx.x;   // 0..127: finalize column `col`
    float fs = sm_s[col] + sm_s[128 + col] + sm_s[256 + col] + sm_s[384 + col];
    float fq = sm_q[col] + sm_q[128 + col] + sm_q[256 + col] + sm_q[384 + col];
    float fx = fmaxf(fmaxf(sm_x[col], sm_x[128 + col]), fmaxf(sm_x[256 + col], sm_x[384 + col]));
    float fn = fminf(fminf(sm_n[col], sm_n[128 + col]), fminf(sm_n[256 + col], sm_n[384 + col]));

    float c    = fmaxf((float)len, 1.f);
    float mean = fs / c;
    float var  = fq / c - mean * mean;
    float stdv = sqrtf(fmaxf(var, 0.f) + 1e-5f);

    float* dst = d_aggr + (size_t)g * 512;
    dst[col]        = mean;
    dst[128 + col]  = stdv;
    dst[256 + col]  = fx;
    dst[384 + col]  = fn;
}

// ---------------- kernel B: fused MLP + LayerNorm + head + tail ----------------
// One block per 8 groups, 256 threads, 512 blocks.
// GEMM1 j-blocked 4-wide: each smem `a` load feeds 4 (pass0) / 3 (pass1) j-columns.
__global__ __launch_bounds__(256) void fused_kernel(
    const float* __restrict__ b1,
    const float* __restrict__ lng, const float* __restrict__ lnb,
    const float* __restrict__ W2, const float* __restrict__ b2,
    const float* __restrict__ u, float* __restrict__ out) {

    __shared__ __align__(16) float aggrT[8 * 512];       // [g][k]  (straight copy)
    __shared__ __align__(16) float hraw [8 * 52];        // [g][j]
    __shared__ __align__(16) float hnT  [50 * 8 + 8];    // [j][g]

    int tid   = threadIdx.x;
    int lane  = tid & 31;
    int wrp   = tid >> 5;            // 0..7
    int gbase = blockIdx.x * 8;

    // ---- stage 1: copy aggr rows for 8 groups into smem (coalesced float4) ----
    {
        const float4* src = reinterpret_cast<const float4*>(d_aggr) + (size_t)gbase * 128;
        float4* dst = reinterpret_cast<float4*>(aggrT);
#pragma unroll
        for (int e = 0; e < 4; e++)
            dst[e * 256 + tid] = __ldg(&src[e * 256 + tid]);
    }
    __syncthreads();

    // ---- stage 2: GEMM1  h[g][j] = selu(sum_k aggr[g][k]*W1[k][j] + b1[j]) ----
    // Warp handles 4 j-columns per pass: j = wrp + 8*s (+32 on pass 1).
    const float SC = 1.0507009873554805f, AL = 1.6732632423543772f;
#pragma unroll
    for (int pass = 0; pass < 2; pass++) {
        const int NS = (pass == 0) ? 4 : 3;     // pass1: j = wrp+32/+40/+48
        int jbase = wrp + pass * 32;
        float pg[4][8];
#pragma unroll
        for (int s = 0; s < 4; s++)
#pragma unroll
            for (int g = 0; g < 8; g++) pg[s][g] = 0.f;

#pragma unroll
        for (int it = 0; it < 4; it++) {
            int k = it * 128 + lane * 4;
            float4 w[4];
#pragma unroll
            for (int s = 0; s < NS; s++) {
                int j = jbase + 8 * s;
                w[s] = (j < HID)
                     ? __ldg(reinterpret_cast<const float4*>(d_W1t + j * 512 + k))
                     : make_float4(0.f, 0.f, 0.f, 0.f);
            }
#pragma unroll
            for (int g = 0; g < 8; g++) {
                float4 a = *reinterpret_cast<const float4*>(&aggrT[g * 512 + k]);
#pragma unroll
                for (int s = 0; s < NS; s++) {
                    pg[s][g] = fmaf(w[s].x, a.x, fmaf(w[s].y, a.y,
                               fmaf(w[s].z, a.z, fmaf(w[s].w, a.w, pg[s][g]))));
                }
            }
        }
#pragma unroll
        for (int s = 0; s < NS; s++) {
            int j = jbase + 8 * s;
#pragma unroll
            for (int o = 16; o > 0; o >>= 1)
#pragma unroll
                for (int g = 0; g < 8; g++)
                    pg[s][g] += __shfl_xor_sync(0xffffffffu, pg[s][g], o);
            if (lane < 8 && j < HID) {
                float v = pg[s][lane] + __ldg(&b1[j]);
                hraw[lane * 52 + j] = v > 0.f ? SC * v : SC * AL * expm1f(v);
            }
        }
    }
    __syncthreads();

    // ---- stage 3: LayerNorm over HID=50, warp w handles group w ----
    {
        int g = wrp;
        float v0 = (lane < HID)      ? hraw[g * 52 + lane]      : 0.f;
        float v1 = (lane + 32 < HID) ? hraw[g * 52 + lane + 32] : 0.f;
        float sm  = v0 + v1;
        float sq2 = v0 * v0 + v1 * v1;
#pragma unroll
        for (int o = 16; o > 0; o >>= 1) {
            sm  += __shfl_xor_sync(0xffffffffu, sm,  o);
            sq2 += __shfl_xor_sync(0xffffffffu, sq2, o);
        }
        float mu  = sm * (1.f / HID);
        float var = sq2 * (1.f / HID) - mu * mu;
        float rs  = rsqrtf(var + 1e-5f);
        if (lane < HID)
            hnT[lane * 8 + g] = (v0 - mu) * rs * lng[lane] + lnb[lane];
        if (lane + 32 < HID)
            hnT[(lane + 32) * 8 + g] = (v1 - mu) * rs * lng[lane + 32] + lnb[lane + 32];
    }
    __syncthreads();

    // ---- stage 4: GEMM2  head = hn @ W2 + b2  (thread: 2 groups x 4 col-slots) ----
    {
        int c0 = tid & 63;          // cols c0, c0+64, c0+128, (c0+192 if c0<9)
        int gq = tid >> 6;          // 0..3 -> groups gq*2, gq*2+1
        bool c3ok = (c0 + 192 < GDIM);
        float acc[2][4];
#pragma unroll
        for (int t = 0; t < 2; t++)
#pragma unroll
            for (int ci = 0; ci < 4; ci++) acc[t][ci] = 0.f;

#pragma unroll 5
        for (int j = 0; j < HID; j++) {
            float2 h2 = *reinterpret_cast<const float2*>(&hnT[j * 8 + gq * 2]);
            const float* w2r = W2 + j * GDIM;
            float w0  = __ldg(&w2r[c0]);
            float w1  = __ldg(&w2r[c0 + 64]);
            float w2v = __ldg(&w2r[c0 + 128]);
            float w3  = c3ok ? __ldg(&w2r[c0 + 192]) : 0.f;
            acc[0][0] = fmaf(h2.x, w0, acc[0][0]); acc[0][1] = fmaf(h2.x, w1, acc[0][1]);
            acc[0][2] = fmaf(h2.x, w2v, acc[0][2]); acc[0][3] = fmaf(h2.x, w3, acc[0][3]);
            acc[1][0] = fmaf(h2.y, w0, acc[1][0]); acc[1][1] = fmaf(h2.y, w1, acc[1][1]);
            acc[1][2] = fmaf(h2.y, w2v, acc[1][2]); acc[1][3] = fmaf(h2.y, w3, acc[1][3]);
        }
        float bb0 = __ldg(&b2[c0]), bb1 = __ldg(&b2[c0 + 64]), bb2 = __ldg(&b2[c0 + 128]);
        float bb3 = c3ok ? __ldg(&b2[c0 + 192]) : 0.f;
#pragma unroll
        for (int t = 0; t < 2; t++) {
            int g = gbase + gq * 2 + t;
            size_t row = (size_t)g * OUTC;
            out[row + c0]        = acc[t][0] + bb0;
            out[row + c0 + 64]   = acc[t][1] + bb1;
            out[row + c0 + 128]  = acc[t][2] + bb2;
            if (c3ok) out[row + c0 + 192] = acc[t][3] + bb3;
        }
    }

    // ---- stage 5: tail = u[:, -33:] ----
    for (int e = tid; e < 8 * TAILC; e += 256) {
        int lg = e / TAILC;
        int t  = e % TAILC;
        int g  = gbase + lg;
        out[(size_t)g * OUTC + GDIM + t] = __ldg(&u[g * 64 + 31 + t]);
    }
}

// ---------------- launch ----------------
extern "C" void kernel_launch(void* const* d_in, const int* in_sizes, int n_in,
                              void* d_out, int out_size) {
    const float* x     = (const float*)d_in[0];
    // d_in[1] edge_index, d_in[2] edge_attr: unused by reference
    const float* u     = (const float*)d_in[3];
    const int*   batch = (const int*)  d_in[4];
    const float* W1    = (const float*)d_in[5];
    const float* b1    = (const float*)d_in[6];
    const float* lng   = (const float*)d_in[7];
    const float* lnb   = (const float*)d_in[8];
    const float* W2    = (const float*)d_in[9];
    const float* b2    = (const float*)d_in[10];
    float* out = (float*)d_out;

    bounds_kernel<<<Nn / 4 / 256, 256>>>(batch);
    w1t_kernel<<<HID, 512>>>(W1);
    seg_kernel<<<Gg, 128>>>((const float4*)x);
    fused_kernel<<<Gg / 8, 256>>>(b1, lng, lnb, W2, b2, u, out);
}

// round 8
// speedup vs baseline: 1.0438x; 1.0438x over previous
#include <cuda_runtime.h>
#include <math.h>

#define Nn   1048576
#define Dd   128
#define Gg   4096
#define HID  50
#define GDIM 201
#define TAILC 33
#define OUTC 234   // 201 + 33
#define JPAD 64    // W1t padded rows (HID=50 -> 64, zero-filled)

// ---------------- device scratch (no runtime allocation allowed) ----------------
__device__ int   d_start[Gg + 1];       // segment row boundaries
__device__ float d_aggr [Gg * 512];     // [g][mean(128) | std(128) | max(128) | min(128)]
__device__ float d_W1t  [JPAD * 512];   // W1 transposed + padded: [j][k]

// ---------------- kernel 0: segment boundaries via linear boundary scan ----------------
__global__ __launch_bounds__(256) void bounds_kernel(const int* __restrict__ batch) {
    int i = blockIdx.x * 256 + threadIdx.x;          // 0 .. Nn/4-1
    const int4* b4 = reinterpret_cast<const int4*>(batch);
    int4 b = __ldg(&b4[i]);
    int prev = (i == 0) ? -1 : __ldg(&batch[i * 4 - 1]);

    int pos = i * 4;
    for (int g = prev + 1; g <= b.x; g++) d_start[g] = pos;
    for (int g = b.x  + 1; g <= b.y; g++) d_start[g] = pos + 1;
    for (int g = b.y  + 1; g <= b.z; g++) d_start[g] = pos + 2;
    for (int g = b.z  + 1; g <= b.w; g++) d_start[g] = pos + 3;

    if (i == Nn / 4 - 1) {
        for (int g = b.w + 1; g <= Gg; g++) d_start[g] = Nn;
    }
}

// ---------------- kernel 0b: transpose W1 [512][50] -> [64][512] zero-padded ----------------
__global__ __launch_bounds__(512) void w1t_kernel(const float* __restrict__ W1) {
    int j = blockIdx.x;            // 0..63
    int k = threadIdx.x;           // 0..511
    d_W1t[j * 512 + k] = (j < HID) ? __ldg(&W1[k * HID + j]) : 0.f;
}

// ---------------- kernel A: one block per segment, software-pipelined loads ----------------
__global__ __launch_bounds__(128) void seg_kernel(const float4* __restrict__ x4) {
    __shared__ __align__(16) float sm_s[512];
    __shared__ __align__(16) float sm_q[512];
    __shared__ __align__(16) float sm_x[512];
    __shared__ __align__(16) float sm_n[512];

    int g    = blockIdx.x;
    int lane = threadIdx.x & 31;
    int w    = threadIdx.x >> 5;

    int lo  = d_start[g];
    int hi  = d_start[g + 1];
    int len = hi - lo;
    int chunk = (len + 3) >> 2;
    int rb = lo + w * chunk;
    int re = min(rb + chunk, hi);
    int nrows = max(re - rb, 0);
    int nit   = nrows >> 2;          // groups of 4 rows

    float4 s  = make_float4(0.f, 0.f, 0.f, 0.f);
    float4 q  = make_float4(0.f, 0.f, 0.f, 0.f);
    float4 mx = make_float4(-INFINITY, -INFINITY, -INFINITY, -INFINITY);
    float4 mn = make_float4( INFINITY,  INFINITY,  INFINITY,  INFINITY);

#define ACC(V)                                                                  \
        s.x += (V).x; s.y += (V).y; s.z += (V).z; s.w += (V).w;                 \
        q.x = fmaf((V).x,(V).x,q.x); q.y = fmaf((V).y,(V).y,q.y);               \
        q.z = fmaf((V).z,(V).z,q.z); q.w = fmaf((V).w,(V).w,q.w);               \
        mx.x = fmaxf(mx.x,(V).x); mx.y = fmaxf(mx.y,(V).y);                     \
        mx.z = fmaxf(mx.z,(V).z); mx.w = fmaxf(mx.w,(V).w);                     \
        mn.x = fminf(mn.x,(V).x); mn.y = fminf(mn.y,(V).y);                     \
        mn.z = fminf(mn.z,(V).z); mn.w = fminf(mn.w,(V).w);

    const float4* p = x4 + (size_t)rb * 32 + lane;

    if (nit > 0) {
        float4 a0 = __ldg(p);
        float4 a1 = __ldg(p + 32);
        float4 a2 = __ldg(p + 64);
        float4 a3 = __ldg(p + 96);
        p += 128;
#pragma unroll 1
        for (int t = 1; t < nit; t++) {
            float4 n0 = __ldg(p);
            float4 n1 = __ldg(p + 32);
            float4 n2 = __ldg(p + 64);
            float4 n3 = __ldg(p + 96);
            p += 128;
            ACC(a0) ACC(a1) ACC(a2) ACC(a3)
            a0 = n0; a1 = n1; a2 = n2; a3 = n3;
        }
        ACC(a0) ACC(a1) ACC(a2) ACC(a3)
    }
    for (int r = rb + nit * 4; r < re; r++) {
        float4 v = __ldg(p);
        p += 32;
        ACC(v)
    }
#undef ACC

    reinterpret_cast<float4*>(sm_s)[w * 32 + lane] = s;
    reinterpret_cast<float4*>(sm_q)[w * 32 + lane] = q;
    reinterpret_cast<float4*>(sm_x)[w * 32 + lane] = mx;
    reinterpret_cast<float4*>(sm_n)[w * 32 + lane] = mn;
    __syncthreads();

    int col = threadIdx.x;   // 0..127: finalize column `col`
    float fs = sm_s[col] + sm_s[128 + col] + sm_s[256 + col] + sm_s[384 + col];
    float fq = sm_q[col] + sm_q[128 + col] + sm_q[256 + col] + sm_q[384 + col];
    float fx = fmaxf(fmaxf(sm_x[col], sm_x[128 + col]), fmaxf(sm_x[256 + col], sm_x[384 + col]));
    float fn = fminf(fminf(sm_n[col], sm_n[128 + col]), fminf(sm_n[256 + col], sm_n[384 + col]));

    float c    = fmaxf((float)len, 1.f);
    float mean = fs / c;
    float var  = fq / c - mean * mean;
    float stdv = sqrtf(fmaxf(var, 0.f) + 1e-5f);

    float* dst = d_aggr + (size_t)g * 512;
    dst[col]        = mean;
    dst[128 + col]  = stdv;
    dst[256 + col]  = fx;
    dst[384 + col]  = fn;
}

// ---------------- kernel B: fused MLP + LayerNorm + head + tail ----------------
// One block per 8 groups, 256 threads, 512 blocks.
// GEMM1: warp owns 7 j-columns (j = wrp + 8s, zero-padded W1t); per k-chunk the
// 8 group activations are loaded from smem ONCE into registers, then 7 weight
// rows stream over them (7 independent LDG.128 in flight, 224 FMA per chunk).
__global__ __launch_bounds__(256) void fused_kernel(
    const float* __restrict__ b1,
    const float* __restrict__ lng, const float* __restrict__ lnb,
    const float* __restrict__ W2, const float* __restrict__ b2,
    const float* __restrict__ u, float* __restrict__ out) {

    __shared__ __align__(16) float aggrT[8 * 512];       // [g][k]  (straight copy)
    __shared__ __align__(16) float hraw [8 * 52];        // [g][j]
    __shared__ __align__(16) float hnT  [50 * 8 + 8];    // [j][g]

    int tid   = threadIdx.x;
    int lane  = tid & 31;
    int wrp   = tid >> 5;            // 0..7
    int gbase = blockIdx.x * 8;

    // ---- stage 1: copy aggr rows for 8 groups into smem (coalesced float4) ----
    {
        const float4* src = reinterpret_cast<const float4*>(d_aggr) + (size_t)gbase * 128;
        float4* dst = reinterpret_cast<float4*>(aggrT);
#pragma unroll
        for (int e = 0; e < 4; e++)
            dst[e * 256 + tid] = __ldg(&src[e * 256 + tid]);
    }
    __syncthreads();

    // ---- stage 2: GEMM1  h[g][j] = selu(sum_k aggr[g][k]*W1[k][j] + b1[j]) ----
    const float SC = 1.0507009873554805f, AL = 1.6732632423543772f;
    {
        float pg[7][8];
#pragma unroll
        for (int s = 0; s < 7; s++)
#pragma unroll
            for (int g = 0; g < 8; g++) pg[s][g] = 0.f;

#pragma unroll
        for (int it = 0; it < 4; it++) {
            int k = it * 128 + lane * 4;
            // load 8 group activations for this k ONCE
            float4 a[8];
#pragma unroll
            for (int g = 0; g < 8; g++)
                a[g] = *reinterpret_cast<const float4*>(&aggrT[g * 512 + k]);
            // stream 7 weight rows over them
#pragma unroll
            for (int s = 0; s < 7; s++) {
                int j = wrp + 8 * s;                 // < 64 (padded)
                float4 w4 = __ldg(reinterpret_cast<const float4*>(d_W1t + j * 512 + k));
#pragma unroll
                for (int g = 0; g < 8; g++) {
                    pg[s][g] = fmaf(w4.x, a[g].x, fmaf(w4.y, a[g].y,
                               fmaf(w4.z, a[g].z, fmaf(w4.w, a[g].w, pg[s][g]))));
                }
            }
        }
#pragma unroll
        for (int s = 0; s < 7; s++) {
#pragma unroll
            for (int o = 16; o > 0; o >>= 1)
#pragma unroll
                for (int g = 0; g < 8; g++)
                    pg[s][g] += __shfl_xor_sync(0xffffffffu, pg[s][g], o);
            int j = wrp + 8 * s;
            if (lane < 8 && j < HID) {
                float v = pg[s][lane] + __ldg(&b1[j]);
                hraw[lane * 52 + j] = v > 0.f ? SC * v : SC * AL * expm1f(v);
            }
        }
    }
    __syncthreads();

    // ---- stage 3: LayerNorm over HID=50, warp w handles group w ----
    {
        int g = wrp;
        float v0 = (lane < HID)      ? hraw[g * 52 + lane]      : 0.f;
        float v1 = (lane + 32 < HID) ? hraw[g * 52 + lane + 32] : 0.f;
        float sm  = v0 + v1;
        float sq2 = v0 * v0 + v1 * v1;
#pragma unroll
        for (int o = 16; o > 0; o >>= 1) {
            sm  += __shfl_xor_sync(0xffffffffu, sm,  o);
            sq2 += __shfl_xor_sync(0xffffffffu, sq2, o);
        }
        float mu  = sm * (1.f / HID);
        float var = sq2 * (1.f / HID) - mu * mu;
        float rs  = rsqrtf(var + 1e-5f);
        if (lane < HID)
            hnT[lane * 8 + g] = (v0 - mu) * rs * lng[lane] + lnb[lane];
        if (lane + 32 < HID)
            hnT[(lane + 32) * 8 + g] = (v1 - mu) * rs * lng[lane + 32] + lnb[lane + 32];
    }
    __syncthreads();

    // ---- stage 4: GEMM2  head = hn @ W2 + b2  (thread: 2 groups x 4 col-slots) ----
    {
        int c0 = tid & 63;          // cols c0, c0+64, c0+128, (c0+192 if c0<9)
        int gq = tid >> 6;          // 0..3 -> groups gq*2, gq*2+1
        bool c3ok = (c0 + 192 < GDIM);
        float acc[2][4];
#pragma unroll
        for (int t = 0; t < 2; t++)
#pragma unroll
            for (int ci = 0; ci < 4; ci++) acc[t][ci] = 0.f;

#pragma unroll 5
        for (int j = 0; j < HID; j++) {
            float2 h2 = *reinterpret_cast<const float2*>(&hnT[j * 8 + gq * 2]);
            const float* w2r = W2 + j * GDIM;
            float w0  = __ldg(&w2r[c0]);
            float w1  = __ldg(&w2r[c0 + 64]);
            float w2v = __ldg(&w2r[c0 + 128]);
            float w3  = c3ok ? __ldg(&w2r[c0 + 192]) : 0.f;
            acc[0][0] = fmaf(h2.x, w0, acc[0][0]); acc[0][1] = fmaf(h2.x, w1, acc[0][1]);
            acc[0][2] = fmaf(h2.x, w2v, acc[0][2]); acc[0][3] = fmaf(h2.x, w3, acc[0][3]);
            acc[1][0] = fmaf(h2.y, w0, acc[1][0]); acc[1][1] = fmaf(h2.y, w1, acc[1][1]);
            acc[1][2] = fmaf(h2.y, w2v, acc[1][2]); acc[1][3] = fmaf(h2.y, w3, acc[1][3]);
        }
        float bb0 = __ldg(&b2[c0]), bb1 = __ldg(&b2[c0 + 64]), bb2 = __ldg(&b2[c0 + 128]);
        float bb3 = c3ok ? __ldg(&b2[c0 + 192]) : 0.f;
#pragma unroll
        for (int t = 0; t < 2; t++) {
            int g = gbase + gq * 2 + t;
            size_t row = (size_t)g * OUTC;
            out[row + c0]        = acc[t][0] + bb0;
            out[row + c0 + 64]   = acc[t][1] + bb1;
            out[row + c0 + 128]  = acc[t][2] + bb2;
            if (c3ok) out[row + c0 + 192] = acc[t][3] + bb3;
        }
    }

    // ---- stage 5: tail = u[:, -33:] ----
    for (int e = tid; e < 8 * TAILC; e += 256) {
        int lg = e / TAILC;
        int t  = e % TAILC;
        int g  = gbase + lg;
        out[(size_t)g * OUTC + GDIM + t] = __ldg(&u[g * 64 + 31 + t]);
    }
}

// ---------------- launch ----------------
extern "C" void kernel_launch(void* const* d_in, const int* in_sizes, int n_in,
                              void* d_out, int out_size) {
    const float* x     = (const float*)d_in[0];
    // d_in[1] edge_index, d_in[2] edge_attr: unused by reference
    const float* u     = (const float*)d_in[3];
    const int*   batch = (const int*)  d_in[4];
    const float* W1    = (const float*)d_in[5];
    const float* b1    = (const float*)d_in[6];
    const float* lng   = (const float*)d_in[7];
    const float* lnb   = (const float*)d_in[8];
    const float* W2    = (const float*)d_in[9];
    const float* b2    = (const float*)d_in[10];
    float* out = (float*)d_out;

    bounds_kernel<<<Nn / 4 / 256, 256>>>(batch);
    w1t_kernel<<<JPAD, 512>>>(W1);
    seg_kernel<<<Gg, 128>>>((const float4*)x);
    fused_kernel<<<Gg / 8, 256>>>(b1, lng, lnb, W2, b2, u, out);
}

// round 9
// speedup vs baseline: 1.1489x; 1.1007x over previous
#include <cuda_runtime.h>
#include <math.h>

#define Nn   1048576
#define Dd   128
#define Gg   4096
#define HID  50
#define GDIM 201
#define TAILC 33
#define OUTC 234   // 201 + 33
#define JPAD 64    // W1t padded rows (HID=50 -> 64, zero-filled)

// ---------------- device scratch (no runtime allocation allowed) ----------------
__device__ int   d_start[Gg + 1];       // segment row boundaries
__device__ float d_aggr [Gg * 512];     // [g][mean(128) | std(128) | max(128) | min(128)]
__device__ float d_W1t  [JPAD * 512];   // W1 transposed + padded: [j][k]

// ---------------- kernel 0: segment boundaries via linear boundary scan ----------------
__global__ __launch_bounds__(256) void bounds_kernel(const int* __restrict__ batch) {
    int i = blockIdx.x * 256 + threadIdx.x;          // 0 .. Nn/4-1
    const int4* b4 = reinterpret_cast<const int4*>(batch);
    int4 b = __ldg(&b4[i]);
    int prev = (i == 0) ? -1 : __ldg(&batch[i * 4 - 1]);

    int pos = i * 4;
    for (int g = prev + 1; g <= b.x; g++) d_start[g] = pos;
    for (int g = b.x  + 1; g <= b.y; g++) d_start[g] = pos + 1;
    for (int g = b.y  + 1; g <= b.z; g++) d_start[g] = pos + 2;
    for (int g = b.z  + 1; g <= b.w; g++) d_start[g] = pos + 3;

    if (i == Nn / 4 - 1) {
        for (int g = b.w + 1; g <= Gg; g++) d_start[g] = Nn;
    }
}

// ---------------- kernel 0b: transpose W1 [512][50] -> [64][512] zero-padded ----------------
__global__ __launch_bounds__(512) void w1t_kernel(const float* __restrict__ W1) {
    int j = blockIdx.x;            // 0..63
    int k = threadIdx.x;           // 0..511
    d_W1t[j * 512 + k] = (j < HID) ? __ldg(&W1[k * HID + j]) : 0.f;
}

// ---------------- kernel A: one block per segment, software-pipelined loads ----------------
__global__ __launch_bounds__(128) void seg_kernel(const float4* __restrict__ x4) {
    __shared__ __align__(16) float sm_s[512];
    __shared__ __align__(16) float sm_q[512];
    __shared__ __align__(16) float sm_x[512];
    __shared__ __align__(16) float sm_n[512];

    int g    = blockIdx.x;
    int lane = threadIdx.x & 31;
    int w    = threadIdx.x >> 5;

    int lo  = d_start[g];
    int hi  = d_start[g + 1];
    int len = hi - lo;
    int chunk = (len + 3) >> 2;
    int rb = lo + w * chunk;
    int re = min(rb + chunk, hi);
    int nrows = max(re - rb, 0);
    int nit   = nrows >> 2;          // groups of 4 rows

    float4 s  = make_float4(0.f, 0.f, 0.f, 0.f);
    float4 q  = make_float4(0.f, 0.f, 0.f, 0.f);
    float4 mx = make_float4(-INFINITY, -INFINITY, -INFINITY, -INFINITY);
    float4 mn = make_float4( INFINITY,  INFINITY,  INFINITY,  INFINITY);

#define ACC(V)                                                                  \
        s.x += (V).x; s.y += (V).y; s.z += (V).z; s.w += (V).w;                 \
        q.x = fmaf((V).x,(V).x,q.x); q.y = fmaf((V).y,(V).y,q.y);               \
        q.z = fmaf((V).z,(V).z,q.z); q.w = fmaf((V).w,(V).w,q.w);               \
        mx.x = fmaxf(mx.x,(V).x); mx.y = fmaxf(mx.y,(V).y);                     \
        mx.z = fmaxf(mx.z,(V).z); mx.w = fmaxf(mx.w,(V).w);                     \
        mn.x = fminf(mn.x,(V).x); mn.y = fminf(mn.y,(V).y);                     \
        mn.z = fminf(mn.z,(V).z); mn.w = fminf(mn.w,(V).w);

    const float4* p = x4 + (size_t)rb * 32 + lane;

    if (nit > 0) {
        float4 a0 = __ldg(p);
        float4 a1 = __ldg(p + 32);
        float4 a2 = __ldg(p + 64);
        float4 a3 = __ldg(p + 96);
        p += 128;
#pragma unroll 1
        for (int t = 1; t < nit; t++) {
            float4 n0 = __ldg(p);
            float4 n1 = __ldg(p + 32);
            float4 n2 = __ldg(p + 64);
            float4 n3 = __ldg(p + 96);
            p += 128;
            ACC(a0) ACC(a1) ACC(a2) ACC(a3)
            a0 = n0; a1 = n1; a2 = n2; a3 = n3;
        }
        ACC(a0) ACC(a1) ACC(a2) ACC(a3)
    }
    for (int r = rb + nit * 4; r < re; r++) {
        float4 v = __ldg(p);
        p += 32;
        ACC(v)
    }
#undef ACC

    reinterpret_cast<float4*>(sm_s)[w * 32 + lane] = s;
    reinterpret_cast<float4*>(sm_q)[w * 32 + lane] = q;
    reinterpret_cast<float4*>(sm_x)[w * 32 + lane] = mx;
    reinterpret_cast<float4*>(sm_n)[w * 32 + lane] = mn;
    __syncthreads();

    int col = threadIdx.x;   // 0..127: finalize column `col`
    float fs = sm_s[col] + sm_s[128 + col] + sm_s[256 + col] + sm_s[384 + col];
    float fq = sm_q[col] + sm_q[128 + col] + sm_q[256 + col] + sm_q[384 + col];
    float fx = fmaxf(fmaxf(sm_x[col], sm_x[128 + col]), fmaxf(sm_x[256 + col], sm_x[384 + col]));
    float fn = fminf(fminf(sm_n[col], sm_n[128 + col]), fminf(sm_n[256 + col], sm_n[384 + col]));

    float c    = fmaxf((float)len, 1.f);
    float mean = fs / c;
    float var  = fq / c - mean * mean;
    float stdv = sqrtf(fmaxf(var, 0.f) + 1e-5f);

    float* dst = d_aggr + (size_t)g * 512;
    dst[col]        = mean;
    dst[128 + col]  = stdv;
    dst[256 + col]  = fx;
    dst[384 + col]  = fn;
}

// ---------------- kernel B: fused MLP + LayerNorm + head + tail ----------------
// One block per 8 groups, 256 threads, 512 blocks.
// GEMM1 j-blocked 2-wide over padded JPAD=64: each warp runs exactly 4 j-pairs
// (j0 = 2*wrp + 16t). Each smem activation load feeds 2 j-columns; weight rows
// are zero-padded so the loop is branch-free; writes guarded by j < HID.
__global__ __launch_bounds__(256) void fused_kernel(
    const float* __restrict__ b1,
    const float* __restrict__ lng, const float* __restrict__ lnb,
    const float* __restrict__ W2, const float* __restrict__ b2,
    const float* __restrict__ u, float* __restrict__ out) {

    __shared__ __align__(16) float aggrT[8 * 512];       // [g][k]  (straight copy)
    __shared__ __align__(16) float hraw [8 * 52];        // [g][j]
    __shared__ __align__(16) float hnT  [50 * 8 + 8];    // [j][g]

    int tid   = threadIdx.x;
    int lane  = tid & 31;
    int wrp   = tid >> 5;            // 0..7
    int gbase = blockIdx.x * 8;

    // ---- stage 1: copy aggr rows for 8 groups into smem (coalesced float4) ----
    {
        const float4* src = reinterpret_cast<const float4*>(d_aggr) + (size_t)gbase * 128;
        float4* dst = reinterpret_cast<float4*>(aggrT);
#pragma unroll
        for (int e = 0; e < 4; e++)
            dst[e * 256 + tid] = __ldg(&src[e * 256 + tid]);
    }
    __syncthreads();

    // ---- stage 2: GEMM1  h[g][j] = selu(sum_k aggr[g][k]*W1[k][j] + b1[j]) ----
    const float SC = 1.0507009873554805f, AL = 1.6732632423543772f;
#pragma unroll 1
    for (int j0 = wrp * 2; j0 < JPAD; j0 += 16) {
        int j1 = j0 + 1;
        float pg0[8], pg1[8];
#pragma unroll
        for (int g = 0; g < 8; g++) { pg0[g] = 0.f; pg1[g] = 0.f; }

#pragma unroll
        for (int it = 0; it < 4; it++) {
            int k = it * 128 + lane * 4;
            float4 w0 = __ldg(reinterpret_cast<const float4*>(d_W1t + j0 * 512 + k));
            float4 w1 = __ldg(reinterpret_cast<const float4*>(d_W1t + j1 * 512 + k));
#pragma unroll
            for (int g = 0; g < 8; g++) {
                float4 a = *reinterpret_cast<const float4*>(&aggrT[g * 512 + k]);
                pg0[g] = fmaf(w0.x, a.x, fmaf(w0.y, a.y,
                         fmaf(w0.z, a.z, fmaf(w0.w, a.w, pg0[g]))));
                pg1[g] = fmaf(w1.x, a.x, fmaf(w1.y, a.y,
                         fmaf(w1.z, a.z, fmaf(w1.w, a.w, pg1[g]))));
            }
        }
#pragma unroll
        for (int o = 16; o > 0; o >>= 1)
#pragma unroll
            for (int g = 0; g < 8; g++) {
                pg0[g] += __shfl_xor_sync(0xffffffffu, pg0[g], o);
                pg1[g] += __shfl_xor_sync(0xffffffffu, pg1[g], o);
            }
        if (lane < 8 && j0 < HID) {
            float v = pg0[lane] + __ldg(&b1[j0]);
            hraw[lane * 52 + j0] = v > 0.f ? SC * v : SC * AL * expm1f(v);
        }
        if (lane < 8 && j1 < HID) {
            float v = pg1[lane] + __ldg(&b1[j1]);
            hraw[lane * 52 + j1] = v > 0.f ? SC * v : SC * AL * expm1f(v);
        }
    }
    __syncthreads();

    // ---- stage 3: LayerNorm over HID=50, warp w handles group w ----
    {
        int g = wrp;
        float v0 = (lane < HID)      ? hraw[g * 52 + lane]      : 0.f;
        float v1 = (lane + 32 < HID) ? hraw[g * 52 + lane + 32] : 0.f;
        float sm  = v0 + v1;
        float sq2 = v0 * v0 + v1 * v1;
#pragma unroll
        for (int o = 16; o > 0; o >>= 1) {
            sm  += __shfl_xor_sync(0xffffffffu, sm,  o);
            sq2 += __shfl_xor_sync(0xffffffffu, sq2, o);
        }
        float mu  = sm * (1.f / HID);
        float var = sq2 * (1.f / HID) - mu * mu;
        float rs  = rsqrtf(var + 1e-5f);
        if (lane < HID)
            hnT[lane * 8 + g] = (v0 - mu) * rs * lng[lane] + lnb[lane];
        if (lane + 32 < HID)
            hnT[(lane + 32) * 8 + g] = (v1 - mu) * rs * lng[lane + 32] + lnb[lane + 32];
    }
    __syncthreads();

    // ---- stage 4: GEMM2  head = hn @ W2 + b2  (thread: 2 groups x 4 col-slots) ----
    {
        int c0 = tid & 63;          // cols c0, c0+64, c0+128, (c0+192 if c0<9)
        int gq = tid >> 6;          // 0..3 -> groups gq*2, gq*2+1
        bool c3ok = (c0 + 192 < GDIM);
        float acc[2][4];
#pragma unroll
        for (int t = 0; t < 2; t++)
#pragma unroll
            for (int ci = 0; ci < 4; ci++) acc[t][ci] = 0.f;

#pragma unroll 5
        for (int j = 0; j < HID; j++) {
            float2 h2 = *reinterpret_cast<const float2*>(&hnT[j * 8 + gq * 2]);
            const float* w2r = W2 + j * GDIM;
            float w0  = __ldg(&w2r[c0]);
            float w1  = __ldg(&w2r[c0 + 64]);
            float w2v = __ldg(&w2r[c0 + 128]);
            float w3  = c3ok ? __ldg(&w2r[c0 + 192]) : 0.f;
            acc[0][0] = fmaf(h2.x, w0, acc[0][0]); acc[0][1] = fmaf(h2.x, w1, acc[0][1]);
            acc[0][2] = fmaf(h2.x, w2v, acc[0][2]); acc[0][3] = fmaf(h2.x, w3, acc[0][3]);
            acc[1][0] = fmaf(h2.y, w0, acc[1][0]); acc[1][1] = fmaf(h2.y, w1, acc[1][1]);
            acc[1][2] = fmaf(h2.y, w2v, acc[1][2]); acc[1][3] = fmaf(h2.y, w3, acc[1][3]);
        }
        float bb0 = __ldg(&b2[c0]), bb1 = __ldg(&b2[c0 + 64]), bb2 = __ldg(&b2[c0 + 128]);
        float bb3 = c3ok ? __ldg(&b2[c0 + 192]) : 0.f;
#pragma unroll
        for (int t = 0; t < 2; t++) {
            int g = gbase + gq * 2 + t;
            size_t row = (size_t)g * OUTC;
            out[row + c0]        = acc[t][0] + bb0;
            out[row + c0 + 64]   = acc[t][1] + bb1;
            out[row + c0 + 128]  = acc[t][2] + bb2;
            if (c3ok) out[row + c0 + 192] = acc[t][3] + bb3;
        }
    }

    // ---- stage 5: tail = u[:, -33:] ----
    for (int e = tid; e < 8 * TAILC; e += 256) {
        int lg = e / TAILC;
        int t  = e % TAILC;
        int g  = gbase + lg;
        out[(size_t)g * OUTC + GDIM + t] = __ldg(&u[g * 64 + 31 + t]);
    }
}

// ---------------- launch ----------------
extern "C" void kernel_launch(void* const* d_in, const int* in_sizes, int n_in,
                              void* d_out, int out_size) {
    const float* x     = (const float*)d_in[0];
    // d_in[1] edge_index, d_in[2] edge_attr: unused by reference
    const float* u     = (const float*)d_in[3];
    const int*   batch = (const int*)  d_in[4];
    const float* W1    = (const float*)d_in[5];
    const float* b1    = (const float*)d_in[6];
    const float* lng   = (const float*)d_in[7];
    const float* lnb   = (const float*)d_in[8];
    const float* W2    = (const float*)d_in[9];
    const float* b2    = (const float*)d_in[10];
    float* out = (float*)d_out;

    bounds_kernel<<<Nn / 4 / 256, 256>>>(batch);
    w1t_kernel<<<JPAD, 512>>>(W1);
    seg_kernel<<<Gg, 128>>>((const float4*)x);
    fused_kernel<<<Gg / 8, 256>>>(b1, lng, lnb, W2, b2, u, out);
}